// round 17
// speedup vs baseline: 7.5201x; 1.0560x over previous
#include <cuda_runtime.h>
#include <cuda_fp16.h>
#include <stdint.h>
#include <math.h>

#define S_LEN 2048
#define HID 4096
#define NH 32
#define NKV 8
#define HD 128

// ---------------- scratch ---------------------------------------------------
__device__ __half g_xh16[S_LEN * HID], g_xl16[S_LEN * HID];
__device__ __half g_wq16[HID * HID];
__device__ __half g_wk16[NKV*HD * HID];
__device__ __half g_wv16[NKV*HD * HID];
__device__ __half g_wo16[HID * HID];
__device__ __half g_att16[S_LEN * HID];
__device__ __half g_vt16[NKV * HD * S_LEN];
__device__ __half g_qh16[NH * S_LEN * HD];
__device__ __half g_k16[NKV * S_LEN * HD];

// ======================= helpers ===========================================
__device__ __forceinline__ uint32_t smem_u32(const void* p) {
    uint32_t a;
    asm("{ .reg .u64 t; cvta.to.shared.u64 t, %1; cvt.u32.u64 %0, t; }" : "=r"(a) : "l"(p));
    return a;
}
__device__ __forceinline__ void cp_async16(uint32_t saddr, const void* g) {
    asm volatile("cp.async.cg.shared.global [%0], [%1], 16;" :: "r"(saddr), "l"(g));
}
#define CP_COMMIT() asm volatile("cp.async.commit_group;" ::: "memory")

#define MMA_F16(c, a, b0, b1)                                                  \
    asm volatile("mma.sync.aligned.m16n8k16.row.col.f32.f16.f16.f32 "          \
        "{%0,%1,%2,%3}, {%4,%5,%6,%7}, {%8,%9}, {%0,%1,%2,%3};"                \
        : "+f"((c)[0]), "+f"((c)[1]), "+f"((c)[2]), "+f"((c)[3])               \
        : "r"((a)[0]), "r"((a)[1]), "r"((a)[2]), "r"((a)[3]), "r"(b0), "r"(b1))

__device__ __forceinline__ void ldsm_x4(uint32_t* r, uint32_t addr) {
    asm volatile("ldmatrix.sync.aligned.m8n8.x4.shared.b16 {%0,%1,%2,%3}, [%4];"
        : "=r"(r[0]), "=r"(r[1]), "=r"(r[2]), "=r"(r[3]) : "r"(addr));
}
__device__ __forceinline__ uint32_t pack2h(float x, float y) {
    __half2 h = __floats2half2_rn(x, y);
    return *(uint32_t*)&h;
}

// ======================= one-shot split of all inputs (MLP=4) ==============
#define X4  ((S_LEN * HID) / 4)
#define W44 ((HID * HID) / 4)
#define W14 ((NKV * HD * HID) / 4)
#define SPLIT_TOTAL (X4 + 2 * W44 + 2 * W14)

__global__ void split_all(const float4* __restrict__ x,
                          uint2* __restrict__ xh, uint2* __restrict__ xl,
                          const float4* __restrict__ wq, uint2* __restrict__ wqo,
                          const float4* __restrict__ wk, uint2* __restrict__ wko,
                          const float4* __restrict__ wv, uint2* __restrict__ wvo,
                          const float4* __restrict__ wo, uint2* __restrict__ woo) {
    const int base = blockIdx.x * 1024 + threadIdx.x;
    const int A = X4, B = A + W44, C = B + W14, D = C + W14;
#pragma unroll
    for (int u = 0; u < 4; u++) {
        const int i = base + u * 256;
        if (i >= SPLIT_TOTAL) break;
        if (i < A) {
            float4 v = x[i];
            __half h[4], l[4];
            h[0] = __float2half_rn(v.x); l[0] = __float2half_rn(v.x - __half2float(h[0]));
            h[1] = __float2half_rn(v.y); l[1] = __float2half_rn(v.y - __half2float(h[1]));
            h[2] = __float2half_rn(v.z); l[2] = __float2half_rn(v.z - __half2float(h[2]));
            h[3] = __float2half_rn(v.w); l[3] = __float2half_rn(v.w - __half2float(h[3]));
            xh[i] = *(uint2*)h;
            xl[i] = *(uint2*)l;
        } else {
            const float4* src;
            uint2* dst;
            int j;
            if (i < B)      { j = i - A; src = wq; dst = wqo; }
            else if (i < C) { j = i - B; src = wk; dst = wko; }
            else if (i < D) { j = i - C; src = wv; dst = wvo; }
            else            { j = i - D; src = wo; dst = woo; }
            float4 v = src[j];
            __half h[4];
            h[0] = __float2half_rn(v.x);
            h[1] = __float2half_rn(v.y);
            h[2] = __float2half_rn(v.z);
            h[3] = __float2half_rn(v.w);
            dst[j] = *(uint2*)h;
        }
    }
}

// ======================= common tile constants =============================
#define R64 144
#define T64 (128 * R64)                // 18432 per tile buffer
#define STGQ (2 * T64)                 // 36864 (1-MMA: A,B)
#define STGKV (3 * T64)                // 55296 (K: Xh,Xl,B)
#define PROJ_SMEM (3 * STGQ)           // 110592 (== 2*STGKV); 2 CTAs/SM

// ======================= fused Q+K+V projections (one launch) ==============
//  bid <  128 : K tile (2-MMA, Kc=64, 2-stage, rope epilogue) — heaviest FIRST
//  128..255   : V tile (1-MMA, Kc=64, 3-stage, transpose epilogue)
//  bid >= 256 : Q tile (1-MMA, Kc=64, 3-stage, rope+scale epilogue)
__global__ __launch_bounds__(256, 2) void gemm_all(
    const __half* __restrict__ Xh, const __half* __restrict__ Xl,
    const __half* __restrict__ Wq, const __half* __restrict__ Wk,
    const __half* __restrict__ Wv,
    const float* __restrict__ cs, const float* __restrict__ sn,
    __half* __restrict__ Qo, __half* __restrict__ Ko, __half* __restrict__ Vto,
    float scale)
{
    extern __shared__ char sm[];
    const uint32_t smb = smem_u32(sm);

    const int bid = blockIdx.x;
    const int tid = threadIdx.x;
    const int warp = tid >> 5;
    const int lane = tid & 31;
    const int g = lane >> 2;
    const int t = lane & 3;
    const int K = HID;
    const int nc = K >> 6;             // 64 chunks
    const int wm = warp >> 2;          // 0..1
    const int wn = warp & 3;           // 0..3

    const int a_r  = (lane & 7) + ((lane >> 3) & 1) * 8;
    const int a_c8 = (lane >> 4) * 8;
    const int b_r  = lane & 7;
    const int b_j  = lane >> 4;
    const int b_c8 = ((lane >> 3) & 1) * 8;

    float acc[4][4][4];
#pragma unroll
    for (int i = 0; i < 4; i++)
#pragma unroll
        for (int j = 0; j < 4; j++)
#pragma unroll
            for (int r = 0; r < 4; r++) acc[i][j][r] = 0.0f;

    if (bid >= 128) {
        // ===== Q / V path: 128x128, 1-MMA, Kc=64, 3-stage single-barrier ====
        const bool isQ = bid >= 256;
        int bm, bn;
        const __half* W;
        if (isQ) {
            const int qid = bid - 256;
            bm = (qid >> 5) * 128;
            bn = (qid & 31) * 128;
            W = Wq;
        } else {
            const int vid = bid - 128;
            bm = (vid >> 3) * 128;
            bn = (vid & 7) * 128;
            W = Wv;
        }

        auto load_stage = [&](int s, int c) {
            const uint32_t sb = smb + s * STGQ;
            const int k0 = c * 64;
#pragma unroll
            for (int it = 0; it < 4; it++) {
                const int id = tid + it * 256;       // 0..1023
                const int r = id >> 3, ch = id & 7;
                const uint32_t off = r * R64 + ch * 16;
                cp_async16(sb + off,       Xh + (size_t)(bm + r) * K + k0 + ch * 8);
                cp_async16(sb + T64 + off, W + (size_t)(bn + r) * K + k0 + ch * 8);
            }
            CP_COMMIT();
        };

        load_stage(0, 0);
        load_stage(1, 1);

        for (int c = 0; c < nc; c++) {
            if (c + 1 < nc) asm volatile("cp.async.wait_group 1;" ::: "memory");
            else            asm volatile("cp.async.wait_group 0;" ::: "memory");
            __syncthreads();
            if (c + 2 < nc) load_stage((c + 2) % 3, c + 2);

            const uint32_t uA = smb + (c % 3) * STGQ;
            const uint32_t uB = uA + T64;
#pragma unroll
            for (int ks = 0; ks < 4; ks++) {
                const uint32_t colA = (ks * 16 + a_c8) * 2;
                const uint32_t colB = (ks * 16 + b_c8) * 2;
                uint32_t ah[4][4];
#pragma unroll
                for (int i = 0; i < 4; i++) {
                    const uint32_t ro = (wm * 64 + i * 16 + a_r) * R64 + colA;
                    ldsm_x4(ah[i], uA + ro);
                }
#pragma unroll
                for (int p = 0; p < 2; p++) {
                    const uint32_t ro = (wn * 32 + (2 * p + b_j) * 8 + b_r) * R64 + colB;
                    uint32_t bh[4];
                    ldsm_x4(bh, uB + ro);
#pragma unroll
                    for (int i = 0; i < 4; i++) {
                        MMA_F16(acc[i][2*p],   ah[i], bh[0], bh[1]);
                        MMA_F16(acc[i][2*p+1], ah[i], bh[2], bh[3]);
                    }
                }
            }
        }
        __syncthreads();

        if (isQ) {
            // ---- rope+scale epilogue through smem fp32 staging ----
            float* st = (float*)sm;   // [128][132] fp32
            const int bx = (bid - 256) & 31;
#pragma unroll
            for (int i = 0; i < 4; i++) {
                const int r0 = wm * 64 + i * 16 + g;
#pragma unroll
                for (int j = 0; j < 4; j++) {
                    const int col = wn * 32 + j * 8 + 2 * t;
                    *(float2*)&st[r0 * 132 + col] = make_float2(acc[i][j][0], acc[i][j][1]);
                    *(float2*)&st[(r0 + 8) * 132 + col] = make_float2(acc[i][j][2], acc[i][j][3]);
                }
            }
            __syncthreads();
#pragma unroll
            for (int it = 0; it < 32; it++) {
                const int id = tid + 256 * it;       // 0..8191
                const int srow = id >> 6, d = id & 63;
                const int s = bm + srow;
                const float x1 = st[srow * 132 + d];
                const float x2 = st[srow * 132 + d + 64];
                const float c = cs[s * 64 + d];
                const float si = sn[s * 64 + d];
                const size_t base = ((size_t)bx * S_LEN + s) * HD;
                Qo[base + d]      = __float2half_rn((x1 * c - x2 * si) * scale);
                Qo[base + d + 64] = __float2half_rn((x2 * c + x1 * si) * scale);
            }
        } else {
            // ---- V: fused transpose epilogue -> vt16[kvh][d][s] ----
            __half* st = (__half*)sm;    // [128 d][136 stride] halves
            const int kvh = bn >> 7;
#pragma unroll
            for (int i = 0; i < 4; i++) {
                const int sl = wm * 64 + i * 16 + g;
#pragma unroll
                for (int j = 0; j < 4; j++) {
                    const int d0 = wn * 32 + j * 8 + 2 * t;
                    st[(d0    ) * 136 + sl    ] = __float2half_rn(acc[i][j][0]);
                    st[(d0 + 1) * 136 + sl    ] = __float2half_rn(acc[i][j][1]);
                    st[(d0    ) * 136 + sl + 8] = __float2half_rn(acc[i][j][2]);
                    st[(d0 + 1) * 136 + sl + 8] = __float2half_rn(acc[i][j][3]);
                }
            }
            __syncthreads();
#pragma unroll
            for (int it = 0; it < 8; it++) {
                const int id = tid + 256 * it;      // 0..2047
                const int d = id >> 4, seg = id & 15;
                uint4 val = *(uint4*)&st[d * 136 + seg * 8];
                *(uint4*)(Vto + ((size_t)(kvh * HD + d)) * S_LEN + bm + seg * 8) = val;
            }
        }
    } else {
        // ===== K path: 128x128, 2-MMA, Kc=64, 2-stage =======================
        const int bx = bid & 7;
        const int by = bid >> 3;
        const int bm = by * 128;
        const int bn = bx * 128;

        auto load_stage = [&](int s, int c) {
            const uint32_t sb = smb + s * STGKV;
            const int k0 = c * 64;
#pragma unroll
            for (int it = 0; it < 4; it++) {
                const int id = tid + it * 256;
                const int r = id >> 3, ch = id & 7;
                const uint32_t off = r * R64 + ch * 16;
                const size_t ga = (size_t)(bm + r) * K + k0 + ch * 8;
                const size_t gb = (size_t)(bn + r) * K + k0 + ch * 8;
                cp_async16(sb + off,           Xh + ga);
                cp_async16(sb + T64 + off,     Xl + ga);
                cp_async16(sb + 2 * T64 + off, Wk + gb);
            }
            CP_COMMIT();
        };

        load_stage(0, 0);
        load_stage(1, 1);

        for (int c = 0; c < nc; c++) {
            const int s = c & 1;
            if (c + 1 < nc) asm volatile("cp.async.wait_group 1;" ::: "memory");
            else            asm volatile("cp.async.wait_group 0;" ::: "memory");
            __syncthreads();

            const uint32_t uAh = smb + s * STGKV;
            const uint32_t uAl = uAh + T64;
            const uint32_t uB  = uAh + 2 * T64;
#pragma unroll
            for (int ks = 0; ks < 4; ks++) {
                const uint32_t colA = (ks * 16 + a_c8) * 2;
                const uint32_t colB = (ks * 16 + b_c8) * 2;
                uint32_t ah[4][4], al[4][4];
#pragma unroll
                for (int i = 0; i < 4; i++) {
                    const uint32_t ro = (wm * 64 + i * 16 + a_r) * R64 + colA;
                    ldsm_x4(ah[i], uAh + ro);
                    ldsm_x4(al[i], uAl + ro);
                }
#pragma unroll
                for (int p = 0; p < 2; p++) {
                    const uint32_t ro = (wn * 32 + (2 * p + b_j) * 8 + b_r) * R64 + colB;
                    uint32_t bh[4];
                    ldsm_x4(bh, uB + ro);
#pragma unroll
                    for (int i = 0; i < 4; i++) {
                        MMA_F16(acc[i][2*p],   ah[i], bh[0], bh[1]);
                        MMA_F16(acc[i][2*p],   al[i], bh[0], bh[1]);
                        MMA_F16(acc[i][2*p+1], ah[i], bh[2], bh[3]);
                        MMA_F16(acc[i][2*p+1], al[i], bh[2], bh[3]);
                    }
                }
            }
            __syncthreads();
            if (c + 2 < nc) load_stage(s, c + 2);
        }

        // ---- K: rope epilogue through smem fp32 staging ----
        const int kvh = bn >> 7;
        float* st = (float*)sm;
#pragma unroll
        for (int i = 0; i < 4; i++) {
            const int r0 = wm * 64 + i * 16 + g;
#pragma unroll
            for (int j = 0; j < 4; j++) {
                const int col = wn * 32 + j * 8 + 2 * t;
                *(float2*)&st[r0 * 132 + col] = make_float2(acc[i][j][0], acc[i][j][1]);
                *(float2*)&st[(r0 + 8) * 132 + col] = make_float2(acc[i][j][2], acc[i][j][3]);
            }
        }
        __syncthreads();
#pragma unroll
        for (int it = 0; it < 32; it++) {
            const int id = tid + 256 * it;
            const int srow = id >> 6, d = id & 63;
            const int s = bm + srow;
            const float x1 = st[srow * 132 + d];
            const float x2 = st[srow * 132 + d + 64];
            const float c = cs[s * 64 + d];
            const float si = sn[s * 64 + d];
            const size_t base = ((size_t)kvh * S_LEN + s) * HD;
            Ko[base + d]      = __float2half_rn(x1 * c - x2 * si);
            Ko[base + d + 64] = __float2half_rn(x2 * c + x1 * si);
        }
    }
}

// ======================= 128x128 fp16 1-MMA GEMM (O projection) ============
__global__ __launch_bounds__(256, 2) void gemm_tc128s(
    const __half* __restrict__ A, const __half* __restrict__ B,
    float* __restrict__ C, int M, int N, int K)
{
    extern __shared__ char sm[];
    const uint32_t smb = smem_u32(sm);

    const int tid = threadIdx.x;
    const int warp = tid >> 5;
    const int lane = tid & 31;
    const int wm = warp >> 2;
    const int wn = warp & 3;
    const int g = lane >> 2;
    const int t = lane & 3;
    const int bm = blockIdx.y * 128;
    const int bn = blockIdx.x * 128;
    const int nc = K >> 6;

    const int a_r  = (lane & 7) + ((lane >> 3) & 1) * 8;
    const int a_c8 = (lane >> 4) * 8;
    const int b_r  = lane & 7;
    const int b_j  = lane >> 4;
    const int b_c8 = ((lane >> 3) & 1) * 8;

    float acc[4][4][4];
#pragma unroll
    for (int i = 0; i < 4; i++)
#pragma unroll
        for (int j = 0; j < 4; j++)
#pragma unroll
            for (int r = 0; r < 4; r++) acc[i][j][r] = 0.0f;

    auto load_stage = [&](int s, int c) {
        const uint32_t sb = smb + s * STGQ;
        const int k0 = c * 64;
#pragma unroll
        for (int it = 0; it < 4; it++) {
            const int id = tid + it * 256;
            const int r = id >> 3, ch = id & 7;
            const uint32_t off = r * R64 + ch * 16;
            cp_async16(sb + off,       A + (size_t)(bm + r) * K + k0 + ch * 8);
            cp_async16(sb + T64 + off, B + (size_t)(bn + r) * K + k0 + ch * 8);
        }
        CP_COMMIT();
    };

    load_stage(0, 0);
    if (nc > 1) load_stage(1, 1);

    for (int c = 0; c < nc; c++) {
        if (c + 1 < nc) asm volatile("cp.async.wait_group 1;" ::: "memory");
        else            asm volatile("cp.async.wait_group 0;" ::: "memory");
        __syncthreads();
        if (c + 2 < nc) load_stage((c + 2) % 3, c + 2);

        const uint32_t uA = smb + (c % 3) * STGQ;
        const uint32_t uB = uA + T64;

#pragma unroll
        for (int ks = 0; ks < 4; ks++) {
            const uint32_t colA = (ks * 16 + a_c8) * 2;
            const uint32_t colB = (ks * 16 + b_c8) * 2;
            uint32_t ah[4][4];
#pragma unroll
            for (int i = 0; i < 4; i++) {
                const uint32_t ro = (wm * 64 + i * 16 + a_r) * R64 + colA;
                ldsm_x4(ah[i], uA + ro);
            }
#pragma unroll
            for (int p = 0; p < 2; p++) {
                const uint32_t ro = (wn * 32 + (2 * p + b_j) * 8 + b_r) * R64 + colB;
                uint32_t bh[4];
                ldsm_x4(bh, uB + ro);
#pragma unroll
                for (int i = 0; i < 4; i++) {
                    MMA_F16(acc[i][2*p],   ah[i], bh[0], bh[1]);
                    MMA_F16(acc[i][2*p+1], ah[i], bh[2], bh[3]);
                }
            }
        }
    }

#pragma unroll
    for (int i = 0; i < 4; i++) {
        const int row0 = bm + wm * 64 + i * 16 + g;
#pragma unroll
        for (int j = 0; j < 4; j++) {
            const int col = bn + wn * 32 + j * 8 + 2 * t;
            *(float2*)(C + (size_t)row0 * N + col) = make_float2(acc[i][j][0], acc[i][j][1]);
            *(float2*)(C + (size_t)(row0 + 8) * N + col) = make_float2(acc[i][j][2], acc[i][j][3]);
        }
    }
}

// ======================= Flash attention (all single-fp16 MMA) =============
#define QSTR 272
#define VSTR 144
#define FA_QB (128 * QSTR)
#define FA_KB (64 * QSTR)
#define FA_VB (128 * VSTR)
#define FA_STAGE (FA_KB + FA_VB)
#define FA_SMEM (FA_QB + 2 * FA_STAGE)     // 106496

__global__ __launch_bounds__(256, 2) void flash_attn_tc(
    const __half* __restrict__ Qf, const __half* __restrict__ Kf,
    const __half* __restrict__ Vt, __half* __restrict__ O)
{
    extern __shared__ char fsm[];
    const uint32_t smb = smem_u32(fsm);
    const int qb = gridDim.x - 1 - blockIdx.x;
    const int h  = blockIdx.y;
    const int kvh = h % NKV;
    const int q0 = qb * 128;
    const int tid = threadIdx.x;
    const int w = tid >> 5;
    const int lane = tid & 31;
    const int g = lane >> 2;
    const int t = lane & 3;

    const int a_r  = (lane & 7) + ((lane >> 3) & 1) * 8;
    const int a_c8 = (lane >> 4) * 8;
    const int b_r  = lane & 7;
    const int b_j  = lane >> 4;
    const int b_c8 = ((lane >> 3) & 1) * 8;

#pragma unroll
    for (int it = 0; it < 8; it++) {
        const int id = tid + 256 * it;
        const int r = id >> 4, ch = id & 15;
        const uint32_t off = r * QSTR + ch * 16;
        const size_t gi = ((size_t)h * S_LEN + q0 + r) * HD + ch * 8;
        cp_async16(smb + off, Qf + gi);
    }

    auto fa_load = [&](int s, int jb) {
        const uint32_t sb = smb + FA_QB + s * FA_STAGE;
        const int k0 = jb * 64;
#pragma unroll
        for (int it = 0; it < 4; it++) {
            const int id = tid + 256 * it;
            const int r = id >> 4, ch = id & 15;
            const uint32_t off = r * QSTR + ch * 16;
            const size_t gi = ((size_t)kvh * S_LEN + k0 + r) * HD + ch * 8;
            cp_async16(sb + off, Kf + gi);
        }
#pragma unroll
        for (int it = 0; it < 4; it++) {
            const int id = tid + 256 * it;
            const int r = id >> 3, ch = id & 7;
            const uint32_t off = r * VSTR + ch * 16;
            const size_t gi = ((size_t)kvh * HD + r) * S_LEN + k0 + ch * 8;
            cp_async16(sb + FA_KB + off, Vt + gi);
        }
    };

    const int njb = 2 * qb + 2;
    fa_load(0, 0);
    CP_COMMIT();
    fa_load(1, 1);
    CP_COMMIT();

    float oacc[16][4];
#pragma unroll
    for (int jd = 0; jd < 16; jd++)
#pragma unroll
        for (int r = 0; r < 4; r++) oacc[jd][r] = 0.0f;
    float m0 = -1e30f, m1 = -1e30f, l0 = 0.0f, l1 = 0.0f;

    const uint32_t uQ = smb;

    for (int jb = 0; jb < njb; jb++) {
        const int s = jb & 1;
        if (jb + 1 < njb) asm volatile("cp.async.wait_group 1;" ::: "memory");
        else              asm volatile("cp.async.wait_group 0;" ::: "memory");
        __syncthreads();

        const uint32_t uK = smb + FA_QB + s * FA_STAGE;
        const uint32_t uV = uK + FA_KB;

        float sv[8][4];
#pragma unroll
        for (int j = 0; j < 8; j++)
#pragma unroll
            for (int r = 0; r < 4; r++) sv[j][r] = 0.0f;

#pragma unroll
        for (int kt = 0; kt < 8; kt++) {
            const uint32_t qro = (16 * w + a_r) * QSTR + (kt * 16 + a_c8) * 2;
            uint32_t qh[4];
            ldsm_x4(qh, uQ + qro);
#pragma unroll
            for (int p = 0; p < 4; p++) {
                const uint32_t kro = ((2 * p + b_j) * 8 + b_r) * QSTR + (kt * 16 + b_c8) * 2;
                uint32_t kh[4];
                ldsm_x4(kh, uK + kro);
                MMA_F16(sv[2*p],   qh, kh[0], kh[1]);
                MMA_F16(sv[2*p+1], qh, kh[2], kh[3]);
            }
        }

        if (jb >= 2 * qb) {
            const int r0g = q0 + 16 * w + g;
            const int r1g = r0g + 8;
            const int kg = jb * 64;
#pragma unroll
            for (int j = 0; j < 8; j++) {
                const int c0 = kg + 8 * j + 2 * t, c1 = c0 + 1;
                if (c0 > r0g) sv[j][0] = -1e30f;
                if (c1 > r0g) sv[j][1] = -1e30f;
                if (c0 > r1g) sv[j][2] = -1e30f;
                if (c1 > r1g) sv[j][3] = -1e30f;
            }
        }

        float mn0 = m0, mn1 = m1;
#pragma unroll
        for (int j = 0; j < 8; j++) {
            mn0 = fmaxf(mn0, fmaxf(sv[j][0], sv[j][1]));
            mn1 = fmaxf(mn1, fmaxf(sv[j][2], sv[j][3]));
        }
        mn0 = fmaxf(mn0, __shfl_xor_sync(0xffffffffu, mn0, 1));
        mn0 = fmaxf(mn0, __shfl_xor_sync(0xffffffffu, mn0, 2));
        mn1 = fmaxf(mn1, __shfl_xor_sync(0xffffffffu, mn1, 1));
        mn1 = fmaxf(mn1, __shfl_xor_sync(0xffffffffu, mn1, 2));

        const float corr0 = __expf(m0 - mn0);
        const float corr1 = __expf(m1 - mn1);
        float rs0 = 0.0f, rs1 = 0.0f;
#pragma unroll
        for (int j = 0; j < 8; j++) {
            sv[j][0] = __expf(sv[j][0] - mn0);
            sv[j][1] = __expf(sv[j][1] - mn0);
            sv[j][2] = __expf(sv[j][2] - mn1);
            sv[j][3] = __expf(sv[j][3] - mn1);
            rs0 += sv[j][0] + sv[j][1];
            rs1 += sv[j][2] + sv[j][3];
        }
        rs0 += __shfl_xor_sync(0xffffffffu, rs0, 1);
        rs0 += __shfl_xor_sync(0xffffffffu, rs0, 2);
        rs1 += __shfl_xor_sync(0xffffffffu, rs1, 1);
        rs1 += __shfl_xor_sync(0xffffffffu, rs1, 2);
        l0 = l0 * corr0 + rs0;
        l1 = l1 * corr1 + rs1;
        m0 = mn0; m1 = mn1;

#pragma unroll
        for (int jd = 0; jd < 16; jd++) {
            oacc[jd][0] *= corr0; oacc[jd][1] *= corr0;
            oacc[jd][2] *= corr1; oacc[jd][3] *= corr1;
        }

#pragma unroll
        for (int kt = 0; kt < 4; kt++) {
            uint32_t ph[4];
            ph[0] = pack2h(sv[2*kt][0],   sv[2*kt][1]);
            ph[1] = pack2h(sv[2*kt][2],   sv[2*kt][3]);
            ph[2] = pack2h(sv[2*kt+1][0], sv[2*kt+1][1]);
            ph[3] = pack2h(sv[2*kt+1][2], sv[2*kt+1][3]);
#pragma unroll
            for (int p = 0; p < 8; p++) {
                const uint32_t vro = ((2 * p + b_j) * 8 + b_r) * VSTR + (kt * 16 + b_c8) * 2;
                uint32_t vh[4];
                ldsm_x4(vh, uV + vro);
                MMA_F16(oacc[2*p],   ph, vh[0], vh[1]);
                MMA_F16(oacc[2*p+1], ph, vh[2], vh[3]);
            }
        }

        __syncthreads();
        if (jb + 2 < njb) { fa_load(s, jb + 2); CP_COMMIT(); }
    }

    const float inv0 = 1.0f / l0;
    const float inv1 = 1.0f / l1;
    const int s0 = q0 + 16 * w + g;
    const int s1 = s0 + 8;
#pragma unroll
    for (int jd = 0; jd < 16; jd++) {
        const int d = 8 * jd + 2 * t;
        const size_t i0 = (size_t)s0 * HID + h * HD + d;
        const size_t i1 = (size_t)s1 * HID + h * HD + d;
        *(uint32_t*)(O + i0) = pack2h(oacc[jd][0] * inv0, oacc[jd][1] * inv0);
        *(uint32_t*)(O + i1) = pack2h(oacc[jd][2] * inv1, oacc[jd][3] * inv1);
    }
}

// ======================= launch ============================================
extern "C" void kernel_launch(void* const* d_in, const int* in_sizes, int n_in,
                              void* d_out, int out_size) {
    const float* x  = (const float*)d_in[0];
    const float* wq = (const float*)d_in[1];
    const float* wk = (const float*)d_in[2];
    const float* wv = (const float*)d_in[3];
    const float* wo = (const float*)d_in[4];
    const float* cs = (const float*)d_in[5];
    const float* sn = (const float*)d_in[6];
    float* out = (float*)d_out;

    __half *xh16, *xl16, *wq16, *wk16, *wv16, *wo16, *att16, *vt16, *qh16, *k16;
    cudaGetSymbolAddress((void**)&xh16, g_xh16); cudaGetSymbolAddress((void**)&xl16, g_xl16);
    cudaGetSymbolAddress((void**)&wq16, g_wq16); cudaGetSymbolAddress((void**)&wk16, g_wk16);
    cudaGetSymbolAddress((void**)&wv16, g_wv16); cudaGetSymbolAddress((void**)&wo16, g_wo16);
    cudaGetSymbolAddress((void**)&att16, g_att16);
    cudaGetSymbolAddress((void**)&vt16, g_vt16);
    cudaGetSymbolAddress((void**)&qh16, g_qh16);
    cudaGetSymbolAddress((void**)&k16, g_k16);

    cudaFuncSetAttribute(gemm_all, cudaFuncAttributeMaxDynamicSharedMemorySize, PROJ_SMEM);
    cudaFuncSetAttribute(gemm_tc128s, cudaFuncAttributeMaxDynamicSharedMemorySize, PROJ_SMEM);
    cudaFuncSetAttribute(flash_attn_tc, cudaFuncAttributeMaxDynamicSharedMemorySize, FA_SMEM);

    // one-shot split of all inputs (MLP=4)
    split_all<<<SPLIT_TOTAL / 1024, 256>>>(
        (const float4*)x, (uint2*)xh16, (uint2*)xl16,
        (const float4*)wq, (uint2*)wq16,
        (const float4*)wk, (uint2*)wk16,
        (const float4*)wv, (uint2*)wv16,
        (const float4*)wo, (uint2*)wo16);

    // fused Q+K+V projections (K 2-MMA first, then V/Q 1-MMA), 2 CTAs/SM
    const float scale = 0.08838834764831845f;
    gemm_all<<<768, 256, PROJ_SMEM>>>(
        xh16, xl16, wq16, wk16, wv16, cs, sn, qh16, k16, vt16, scale);

    // tensor-core flash attention
    flash_attn_tc<<<dim3(S_LEN / 128, NH), 256, FA_SMEM>>>(
        qh16, k16, vt16, att16);

    // output projection (Kc=64, 3-stage single-barrier, 2 CTAs/SM)
    gemm_tc128s<<<dim3(HID / 128, S_LEN / 128), 256, PROJ_SMEM>>>(
        att16, wo16, out, S_LEN, HID, HID);
}